// round 1
// baseline (speedup 1.0000x reference)
#include <cuda_runtime.h>
#include <math.h>

#define BS 512
#define NN 256
#define MAXITER 200
#define OMEGA 1.5f

// Scratch (static __device__ arrays: allocation-free per harness rules)
__device__ float g_T[(size_t)BS * NN * NN];  // T[b][j][i] = omega*A[b][i][j]/A[b][i][i], diag = 0
__device__ float g_e0[BS * NN];              // e0 = x_sol - theta
__device__ float g_wovd[BS * NN];            // omega / a_ii
__device__ float g_err0[BS];
__device__ float g_xtol[BS];

// ---------------------------------------------------------------------------
// Kernel 1: per-batch prep — e0, err0 = ||e0||, xtol = ||xs||*rtol, omega/diag
// ---------------------------------------------------------------------------
__global__ void __launch_bounds__(NN) prep_kernel(const float* __restrict__ A,
                                                  const float* __restrict__ xs,
                                                  const float* __restrict__ theta,
                                                  const float* __restrict__ rtol,
                                                  float* __restrict__ out) {
    int b = blockIdx.x, i = threadIdx.x;
    float x  = xs[b * NN + i];
    float e0 = x - theta[b * NN + i];
    g_e0[b * NN + i]   = e0;
    g_wovd[b * NN + i] = OMEGA / A[((size_t)b * NN + i) * NN + i];

    float s1 = e0 * e0, s2 = x * x;
#pragma unroll
    for (int off = 16; off; off >>= 1) {
        s1 += __shfl_xor_sync(0xffffffffu, s1, off);
        s2 += __shfl_xor_sync(0xffffffffu, s2, off);
    }
    __shared__ float r1[8], r2[8];
    if ((i & 31) == 0) { r1[i >> 5] = s1; r2[i >> 5] = s2; }
    __syncthreads();
    if (i == 0) {
        float a1 = 0.f, a2 = 0.f;
#pragma unroll
        for (int w = 0; w < 8; ++w) { a1 += r1[w]; a2 += r2[w]; }
        float err0 = sqrtf(a1);
        g_err0[b] = err0;
        g_xtol[b] = sqrtf(a2) * rtol[b];
        out[(size_t)b * (MAXITER + 1)] = err0;   // column 0 = err0
    }
}

// ---------------------------------------------------------------------------
// Kernel 2: tiled transpose + row-scale: T[b][j][i] = omega*A[b][i][j]/a_ii
// (column j of the scaled matrix becomes a contiguous row of T)
// ---------------------------------------------------------------------------
__global__ void __launch_bounds__(256) transpose_kernel(const float* __restrict__ A) {
    __shared__ float tile[32][33];
    int b  = blockIdx.z;
    int i0 = blockIdx.y * 32;
    int j0 = blockIdx.x * 32;
    const float* Ab = A + (size_t)b * NN * NN;
#pragma unroll
    for (int yy = 0; yy < 32; yy += 8) {
        int i = i0 + threadIdx.y + yy;
        int j = j0 + threadIdx.x;
        float v = Ab[i * NN + j] * g_wovd[b * NN + i];
        if (i == j) v = 0.f;
        tile[threadIdx.y + yy][threadIdx.x] = v;
    }
    __syncthreads();
    float* Tb = g_T + (size_t)b * NN * NN;
#pragma unroll
    for (int yy = 0; yy < 32; yy += 8) {
        int j = j0 + threadIdx.y + yy;   // T row index (= A column)
        int i = i0 + threadIdx.x;        // T col index (= A row)
        Tb[j * NN + i] = tile[threadIdx.x][threadIdx.y + yy];
    }
}

// ---------------------------------------------------------------------------
// Kernel 3: SOR error iteration.  One CTA per batch, thread i owns row i.
//   e_new_i = (1-omega)*e_old_i - sum_{j>i} T[j][i]*e_old_j  (phase U, parallel)
//                               - sum_{j<i} T[j][i]*e_new_j  (phase L, fwd subst)
// Record err_t = ||e_new||; stop when err <= xtol, zero-fill the rest.
// ---------------------------------------------------------------------------
__global__ void __launch_bounds__(NN) sor_kernel(float* __restrict__ out) {
    int b = blockIdx.x, tid = threadIdx.x;
    const float* Tb = g_T + (size_t)b * NN * NN;

    __shared__ float ebuf[2][NN];
    __shared__ float wred[8];
    __shared__ float sbc;

    float eold = g_e0[b * NN + tid];
    ebuf[0][tid] = eold;
    float xtol = g_xtol[b];
    float errp = g_err0[b];
    __syncthreads();

    int cur = 0;
    int t = 1;
    for (; t <= MAXITER; ++t) {
        if (errp <= xtol) break;
        const float* eo  = ebuf[cur];
        float*       ens = ebuf[cur ^ 1];

        // ---- Phase U: acc_i = sum_{j>i} T[j][i] * e_old[j]  (coalesced cols) ----
        float acc = 0.f;
        {
            int jstart = (tid & ~31) + 1;   // warp-uniform start; lanes predicated
#pragma unroll 4
            for (int j = jstart; j < NN; ++j) {
                float tv = (j > tid) ? Tb[j * NN + tid] : 0.f;
                acc = fmaf(tv, eo[j], acc);
            }
        }

        // ---- Phase L: forward substitution, column sweep with 4-deep prefetch ----
        float pf0 = (tid > 0) ? Tb[0 * NN + tid] : 0.f;
        float pf1 = (tid > 1) ? Tb[1 * NN + tid] : 0.f;
        float pf2 = (tid > 2) ? Tb[2 * NN + tid] : 0.f;
        float pf3 = (tid > 3) ? Tb[3 * NN + tid] : 0.f;
        float en = 0.f;
#pragma unroll 4
        for (int k = 0; k < NN; ++k) {
            int kp = k + 4;
            float tn = (kp < NN && tid > kp) ? Tb[kp * NN + tid] : 0.f;
            if (tid == k) { en = (1.0f - OMEGA) * eold - acc; ens[k] = en; }
            __syncthreads();
            float bval = ens[k];
            if (tid > k) acc = fmaf(pf0, bval, acc);
            pf0 = pf1; pf1 = pf2; pf2 = pf3; pf3 = tn;
        }

        // ---- err = ||e_new|| (block reduction) ----
        float v = en * en;
#pragma unroll
        for (int off = 16; off; off >>= 1) v += __shfl_xor_sync(0xffffffffu, v, off);
        if ((tid & 31) == 0) wred[tid >> 5] = v;
        __syncthreads();
        if (tid == 0) {
            float s = 0.f;
#pragma unroll
            for (int w = 0; w < 8; ++w) s += wred[w];
            float err = sqrtf(s);
            sbc = err;
            out[(size_t)b * (MAXITER + 1) + t] = err;
        }
        __syncthreads();
        errp = sbc;
        eold = en;
        cur ^= 1;
    }

    // zero-fill the remaining history slots (reference records 0 once done)
    for (int z = t + tid; z <= MAXITER; z += NN)
        out[(size_t)b * (MAXITER + 1) + z] = 0.f;
}

// ---------------------------------------------------------------------------
extern "C" void kernel_launch(void* const* d_in, const int* in_sizes, int n_in,
                              void* d_out, int out_size) {
    const float* A     = (const float*)d_in[0];
    // d_in[1] = b  — not needed (error-vector formulation)
    const float* xs    = (const float*)d_in[2];
    const float* theta = (const float*)d_in[3];
    const float* rtol  = (const float*)d_in[4];
    // d_in[5] = maxiter (compile-time constant 200)
    float* out = (float*)d_out;

    prep_kernel<<<BS, NN>>>(A, xs, theta, rtol, out);

    dim3 tb(32, 8);
    dim3 tg(NN / 32, NN / 32, BS);
    transpose_kernel<<<tg, tb>>>(A);

    sor_kernel<<<BS, NN>>>(out);
}

// round 2
// speedup vs baseline: 4.8449x; 4.8449x over previous
#include <cuda_runtime.h>
#include <math.h>

#define BS 512
#define NN 256
#define MAXITER 200
#define OMEGA 1.5f
#define NWARP 8
#define RB4 24          // float4 chunks of the row kept in registers (j = 0..95)
#define SB4 40          // float4 chunks of the row kept in smem     (j = 96..255)
// smem layout (floats): eold[256] d[256] wred[8] wred2[8] ctrl[2] pad.. matrix @544, scratch after
#define MAT_OFF   544
#define SCR_OFF   (MAT_OFF + SB4*NN*4)
#define SMEM_FLOATS (SCR_OFF + NWARP*32*33)

__global__ void __launch_bounds__(NN, 1) sor_fused(
    const float* __restrict__ A, const float* __restrict__ xs,
    const float* __restrict__ theta, const float* __restrict__ rtol,
    float* __restrict__ out)
{
    extern __shared__ float sm[];
    float*  eold_s = sm;                  // 256
    float*  d_s    = sm + 256;            // 256
    float*  wred   = sm + 512;            // 8
    float*  wred2  = sm + 520;            // 8
    float*  ctrl   = sm + 528;            // [0]=err bcast, [1]=xtol
    float4* sT4    = (float4*)(sm + MAT_OFF);
    float*  scr    = sm + SCR_OFF;        // 8 * (32*33)

    const int b = blockIdx.x, tid = threadIdx.x;
    const int wid = tid >> 5, lane = tid & 31;
    const float4* eo4 = (const float4*)eold_s;
    const float4* dd4 = (const float4*)d_s;

    // ---------------- load row `tid` of A, scale by omega / a_ii ----------------
    const float*  Ar  = A + ((size_t)b * NN + tid) * NN;
    const float4* Ar4 = (const float4*)Ar;
    const float sc = OMEGA / Ar[tid];
    float4 creg[RB4];
#pragma unroll
    for (int jb = 0; jb < RB4; ++jb) {
        float4 v = Ar4[jb];
        v.x *= sc; v.y *= sc; v.z *= sc; v.w *= sc;
        creg[jb] = v;
    }
#pragma unroll
    for (int jb = 0; jb < SB4; ++jb) {
        float4 v = Ar4[RB4 + jb];
        v.x *= sc; v.y *= sc; v.z *= sc; v.w *= sc;
        sT4[jb * NN + tid] = v;
    }

    // ---------------- e0 = xs - theta, err0 = ||e0||, xtol = ||xs||*rtol --------
    const float xv = xs[b * NN + tid];
    float eold = xv - theta[b * NN + tid];
    eold_s[tid] = eold;
    {
        float s1 = eold * eold, s2 = xv * xv;
#pragma unroll
        for (int o = 16; o; o >>= 1) {
            s1 += __shfl_xor_sync(0xffffffffu, s1, o);
            s2 += __shfl_xor_sync(0xffffffffu, s2, o);
        }
        if (lane == 0) { wred[wid] = s1; wred2[wid] = s2; }
    }
    __syncthreads();
    if (tid == 0) {
        float a1 = 0.f, a2 = 0.f;
#pragma unroll
        for (int w = 0; w < NWARP; ++w) { a1 += wred[w]; a2 += wred2[w]; }
        const float err0 = sqrtf(a1);
        out[(size_t)b * (MAXITER + 1)] = err0;
        ctrl[0] = err0;
        ctrl[1] = sqrtf(a2) * rtol[b];
    }

    // ---------------- build M = (I + strict-lower diag-block)^-1 per warp -------
    // lane r of warp p owns row r of the 32x32 block; scratch row pitch 33.
    float* myscr = scr + wid * (32 * 33);
    {
        float seg[32];
        if (wid < 3) {
#pragma unroll
            for (int q = 0; q < 3; ++q) if (wid == q) {
#pragma unroll
                for (int k = 0; k < 8; ++k) {
                    float4 v = creg[q * 8 + k];
                    seg[4*k+0] = v.x; seg[4*k+1] = v.y; seg[4*k+2] = v.z; seg[4*k+3] = v.w;
                }
            }
        } else {
            const int jb0 = wid * 8 - RB4;
#pragma unroll
            for (int k = 0; k < 8; ++k) {
                float4 v = sT4[(jb0 + k) * NN + tid];
                seg[4*k+0] = v.x; seg[4*k+1] = v.y; seg[4*k+2] = v.z; seg[4*k+3] = v.w;
            }
        }
#pragma unroll
        for (int s = 0; s < 32; ++s) myscr[lane * 33 + s] = seg[s];
    }
    __syncwarp();
    {
        // lane c builds column c of M: M[r][c] = delta - sum_{j<r} N[r][j] M[j][c]
        float mcol[32];
#pragma unroll
        for (int r = 0; r < 32; ++r) mcol[r] = (r == lane) ? 1.f : 0.f;
#pragma unroll
        for (int r = 1; r < 32; ++r) {
            float s = 0.f;
#pragma unroll
            for (int j = 0; j < r; ++j) s = fmaf(myscr[r * 33 + j], mcol[j], s);
            mcol[r] -= s;
        }
        __syncwarp();
#pragma unroll
        for (int r = 0; r < 32; ++r) myscr[r * 33 + lane] = mcol[r];
    }
    __syncwarp();
    float Mrow[32];
#pragma unroll
    for (int c = 0; c < 32; ++c) Mrow[c] = myscr[lane * 33 + c];

    // ---------------- zero own-block entries j in [32*wid, tid] -----------------
    if (wid < 3) {
#pragma unroll
        for (int q = 0; q < 3; ++q) if (wid == q) {
#pragma unroll
            for (int s = 0; s < 32; ++s) {
                const int j = q * 32 + s;
                if (j <= tid) {
                    float4& v = creg[j >> 2];
                    if ((j & 3) == 0) v.x = 0.f;
                    else if ((j & 3) == 1) v.y = 0.f;
                    else if ((j & 3) == 2) v.z = 0.f;
                    else v.w = 0.f;
                }
            }
        }
    } else {
        float* sTf = (float*)sT4;
#pragma unroll
        for (int s = 0; s < 32; ++s) {
            const int j = wid * 32 + s;
            if (j <= tid) {
                const int jb = (j - 96) >> 2;
                sTf[(jb * NN + tid) * 4 + (j & 3)] = 0.f;
            }
        }
    }
    __syncthreads();
    float errp = ctrl[0];
    const float xtol = ctrl[1];

    // ---------------- SOR error iteration --------------------------------------
    int t = 1;
    for (; t <= MAXITER; ++t) {
        if (errp <= xtol) break;

        // Phase A: acc = (1-w)*e_i - sum_j c_ij * e_old_j  (own-block lower zeroed)
        float a0 = 0.f, a1 = 0.f, a2 = 0.f, a3 = 0.f;
#pragma unroll
        for (int jb = 0; jb < RB4; ++jb) {
            const float4 c = creg[jb];
            const float4 e = eo4[jb];
            a0 = fmaf(c.x, e.x, a0); a1 = fmaf(c.y, e.y, a1);
            a2 = fmaf(c.z, e.z, a2); a3 = fmaf(c.w, e.w, a3);
        }
#pragma unroll
        for (int jb = 0; jb < SB4; ++jb) {
            const float4 c = sT4[jb * NN + tid];
            const float4 e = eo4[RB4 + jb];
            a0 = fmaf(c.x, e.x, a0); a1 = fmaf(c.y, e.y, a1);
            a2 = fmaf(c.z, e.z, a2); a3 = fmaf(c.w, e.w, a3);
        }
        float acc = (1.0f - OMEGA) * eold - (a0 + a1) - (a2 + a3);

        float en = 0.f;
        // Phase B: blocked forward solve, 8 barriers, rank-32 corrections via d
#pragma unroll
        for (int p = 0; p < NWARP; ++p) {
            __syncthreads();   // p=0: phase A complete before e_old_s overwritten
            if (p > 0 && wid >= p) {
                const int q = p - 1;
                float b0 = 0.f, b1 = 0.f, b2 = 0.f, b3 = 0.f;
                if (q < 3) {
#pragma unroll
                    for (int k = 0; k < 8; ++k) {
                        const float4 c = creg[q * 8 + k];
                        const float4 dv = dd4[q * 8 + k];
                        b0 = fmaf(c.x, dv.x, b0); b1 = fmaf(c.y, dv.y, b1);
                        b2 = fmaf(c.z, dv.z, b2); b3 = fmaf(c.w, dv.w, b3);
                    }
                } else {
#pragma unroll
                    for (int k = 0; k < 8; ++k) {
                        const float4 c = sT4[(q * 8 - RB4 + k) * NN + tid];
                        const float4 dv = dd4[q * 8 + k];
                        b0 = fmaf(c.x, dv.x, b0); b1 = fmaf(c.y, dv.y, b1);
                        b2 = fmaf(c.z, dv.z, b2); b3 = fmaf(c.w, dv.w, b3);
                    }
                }
                acc -= (b0 + b1) + (b2 + b3);
            }
            if (wid == p) {
                const float r = acc;
                float e = 0.f;
#pragma unroll
                for (int c = 0; c < 32; ++c)
                    e = fmaf(Mrow[c], __shfl_sync(0xffffffffu, r, c), e);
                en = e;
                eold_s[tid] = e;        // safe: phase A done (barrier above)
                d_s[tid]    = e - eold;
            }
        }

        // norm of e_new
        float v = en * en;
#pragma unroll
        for (int o = 16; o; o >>= 1) v += __shfl_xor_sync(0xffffffffu, v, o);
        if (lane == 0) wred[wid] = v;
        __syncthreads();
        if (tid == 0) {
            float s = 0.f;
#pragma unroll
            for (int w = 0; w < NWARP; ++w) s += wred[w];
            const float err = sqrtf(s);
            ctrl[0] = err;
            out[(size_t)b * (MAXITER + 1) + t] = err;
        }
        __syncthreads();
        errp = ctrl[0];
        eold = en;
    }

    // zero-fill remaining history slots
    for (int z = t + tid; z <= MAXITER; z += NN)
        out[(size_t)b * (MAXITER + 1) + z] = 0.f;
}

// ---------------------------------------------------------------------------
extern "C" void kernel_launch(void* const* d_in, const int* in_sizes, int n_in,
                              void* d_out, int out_size) {
    const float* A     = (const float*)d_in[0];
    // d_in[1] = b — not needed (error-vector formulation)
    const float* xs    = (const float*)d_in[2];
    const float* theta = (const float*)d_in[3];
    const float* rtol  = (const float*)d_in[4];
    float* out = (float*)d_out;

    static int smem_set = 0;
    if (!smem_set) {
        cudaFuncSetAttribute(sor_fused, cudaFuncAttributeMaxDynamicSharedMemorySize,
                             SMEM_FLOATS * (int)sizeof(float));
        smem_set = 1;
    }
    sor_fused<<<BS, NN, SMEM_FLOATS * sizeof(float)>>>(A, xs, theta, rtol, out);
}